// round 5
// baseline (speedup 1.0000x reference)
#include <cuda_runtime.h>
#include <cuda_fp16.h>
#include <mma.h>
#include <math.h>

using namespace nvcuda;

// ---------------------------------------------------------------------------
// RiemannianGNN: 2-layer Poincare GNN.
//   per layer: t = (logmap(x) if layer>0 else x)*mask
//              msg = (t@W)*mask        [stored fp16]
//              c   = (sum_k w[n,k]*msg[adj[n,k]])*mask
//              x   = relu(expmap(c)*mask)*mask
// Fusions: logmap of layer 1 fused into agg of layer 0.
// GEMM: tf32 WMMA, persistent blocks (W loaded once), 2 CTAs/SM.
// msg buffer fp16: halves gather L1 wavefronts (agg bound) + writeback.
// ---------------------------------------------------------------------------

#define NMAX 50000
#define DD 128
#define KK 32

__device__ __align__(16) __half g_msg[NMAX * DD];   // fp16 msg buffer
__device__ __align__(16) float  g_x[NMAX * DD];     // fp32 inter-layer x

// ---------------- persistent tf32 WMMA GEMM --------------------------------
// tile: 64 rows x 128 cols, 256 threads (8 warps), warp = 16 rows x 64 cols
#define TROWS 64
#define LDS 136   // padded leading dim (floats)

__global__ __launch_bounds__(256) void gemm_tf32_kernel(
    const float* __restrict__ x, const float* __restrict__ W,
    const float* __restrict__ mask, __half* __restrict__ out,
    int N, int applyInMask)
{
    extern __shared__ float sm[];
    float* Ws = sm;                    // 128 x LDS  (~69.6 KB)
    float* xs = sm + DD * LDS;         // TROWS x LDS (~34.8 KB)

    const int tid = threadIdx.x;

    // ---- load W once per block (convert to tf32) ----
    for (int i = tid; i < DD * DD / 4; i += 256) {
        int r = i >> 5;
        int c4 = i & 31;
        float4 v = ((const float4*)W)[r * 32 + c4];
        float* dst = Ws + r * LDS + c4 * 4;
        dst[0] = wmma::__float_to_tf32(v.x);
        dst[1] = wmma::__float_to_tf32(v.y);
        dst[2] = wmma::__float_to_tf32(v.z);
        dst[3] = wmma::__float_to_tf32(v.w);
    }

    const int w = tid >> 5;
    const int rowWarp = w >> 1;    // 0..3 -> rows rowWarp*16
    const int colWarp = w & 1;     // 0..1 -> cols colWarp*64

    const int nTiles = (N + TROWS - 1) / TROWS;

    for (int tile = blockIdx.x; tile < nTiles; tile += gridDim.x) {
        const int n0 = tile * TROWS;

        __syncthreads();   // protect xs from previous iteration's writeback
        // ---- load 64 x-rows (convert to tf32, zero-pad, optional mask) ----
        for (int i = tid; i < TROWS * DD / 4; i += 256) {
            int r = i >> 5;
            int c4 = i & 31;
            int n = n0 + r;
            float4 v = make_float4(0.f, 0.f, 0.f, 0.f);
            if (n < N) {
                v = ((const float4*)x)[n * 32 + c4];
                if (applyInMask) {
                    float m = mask[n];
                    v.x *= m; v.y *= m; v.z *= m; v.w *= m;
                }
            }
            float* dst = xs + r * LDS + c4 * 4;
            dst[0] = wmma::__float_to_tf32(v.x);
            dst[1] = wmma::__float_to_tf32(v.y);
            dst[2] = wmma::__float_to_tf32(v.z);
            dst[3] = wmma::__float_to_tf32(v.w);
        }
        __syncthreads();

        wmma::fragment<wmma::matrix_a, 16, 16, 8, wmma::precision::tf32, wmma::row_major> aF;
        wmma::fragment<wmma::matrix_b, 16, 16, 8, wmma::precision::tf32, wmma::row_major> bF[4];
        wmma::fragment<wmma::accumulator, 16, 16, 8, float> acc[4];
        #pragma unroll
        for (int j = 0; j < 4; j++) wmma::fill_fragment(acc[j], 0.0f);

        #pragma unroll
        for (int ks = 0; ks < DD / 8; ks++) {
            const int kOff = ks * 8;
            wmma::load_matrix_sync(aF, xs + (rowWarp * 16) * LDS + kOff, LDS);
            #pragma unroll
            for (int j = 0; j < 4; j++)
                wmma::load_matrix_sync(bF[j], Ws + kOff * LDS + colWarp * 64 + j * 16, LDS);
            #pragma unroll
            for (int j = 0; j < 4; j++)
                wmma::mma_sync(acc[j], aF, bF[j], acc[j]);
        }

        // park results in xs (A no longer needed), masked fp16 writeback
        __syncthreads();
        #pragma unroll
        for (int j = 0; j < 4; j++)
            wmma::store_matrix_sync(
                xs + (rowWarp * 16) * LDS + colWarp * 64 + j * 16,
                acc[j], LDS, wmma::mem_row_major);
        __syncthreads();

        for (int i = tid; i < TROWS * 64; i += 256) {   // 64 half2 per row
            int r = i >> 6;
            int c2 = i & 63;
            int n = n0 + r;
            if (n < N) {
                float m = mask[n];
                float2 f;
                f.x = xs[r * LDS + c2 * 2]     * m;
                f.y = xs[r * LDS + c2 * 2 + 1] * m;
                ((half2*)out)[n * 64 + c2] = __float22half2_rn(f);
            }
        }
    }
}

// ---------------- Aggregation + expmap + relu (+ fused logmap) -------------
// one warp per node; lane l holds cols 4l..4l+3; msg rows are fp16 (256B)
__global__ __launch_bounds__(256) void agg_kernel(
    const __half* __restrict__ msg, const int* __restrict__ adj,
    const float* __restrict__ wgt, const float* __restrict__ mask,
    float* __restrict__ out, int N, int fuseLogmap)
{
    const int warp = (blockIdx.x * blockDim.x + threadIdx.x) >> 5;
    const int lane = threadIdx.x & 31;
    if (warp >= N) return;

    const int   myIdx = adj[warp * KK + lane];
    const float myW   = wgt[warp * KK + lane];

    float4 acc = make_float4(0.f, 0.f, 0.f, 0.f);
    #pragma unroll
    for (int j = 0; j < KK; j++) {
        int   nb = __shfl_sync(0xffffffffu, myIdx, j);
        float wj = __shfl_sync(0xffffffffu, myW,   j);
        uint2 raw = __ldg(((const uint2*)(msg + (size_t)nb * DD)) + lane);
        half2 h0 = *(half2*)&raw.x;
        half2 h1 = *(half2*)&raw.y;
        float2 f0 = __half22float2(h0);
        float2 f1 = __half22float2(h1);
        acc.x = fmaf(wj, f0.x, acc.x);
        acc.y = fmaf(wj, f0.y, acc.y);
        acc.z = fmaf(wj, f1.x, acc.z);
        acc.w = fmaf(wj, f1.y, acc.w);
    }

    const float m = mask[warp];
    acc.x *= m; acc.y *= m; acc.z *= m; acc.w *= m;

    // expmap_zero: tanh(clip(||v||,eps,15)) * v / max(||v||,eps)
    float ss = acc.x * acc.x + acc.y * acc.y + acc.z * acc.z + acc.w * acc.w;
    #pragma unroll
    for (int o = 16; o > 0; o >>= 1) ss += __shfl_xor_sync(0xffffffffu, ss, o);
    float n1 = sqrtf(ss);
    float nc1 = fminf(fmaxf(n1, 1e-5f), 15.0f);
    float s1 = tanhf(nc1) / fmaxf(n1, 1e-5f);
    s1 *= m;

    float4 e;
    e.x = acc.x * s1; e.y = acc.y * s1; e.z = acc.z * s1; e.w = acc.w * s1;
    e.x = fmaxf(e.x, 0.f) * m; e.y = fmaxf(e.y, 0.f) * m;
    e.z = fmaxf(e.z, 0.f) * m; e.w = fmaxf(e.w, 0.f) * m;

    if (fuseLogmap) {
        // next layer's logmap: atanh(clip(||y||,eps,1-1e-5)) * y / max(||y||,eps), * mask
        float ss2 = e.x * e.x + e.y * e.y + e.z * e.z + e.w * e.w;
        #pragma unroll
        for (int o = 16; o > 0; o >>= 1) ss2 += __shfl_xor_sync(0xffffffffu, ss2, o);
        float n2 = sqrtf(ss2);
        float nc2 = fminf(fmaxf(n2, 1e-5f), 1.0f - 1e-5f);
        float s2 = atanhf(nc2) / fmaxf(n2, 1e-5f);
        s2 *= m;
        e.x *= s2; e.y *= s2; e.z *= s2; e.w *= s2;
    }

    ((float4*)out)[warp * 32 + lane] = e;
}

// ---------------------------------------------------------------------------

extern "C" void kernel_launch(void* const* d_in, const int* in_sizes, int n_in,
                              void* d_out, int out_size)
{
    const float* node_repr = (const float*)d_in[0];   // [N,128]
    const int*   adj_mat   = (const int*)  d_in[1];   // [N,32]
    const float* weight    = (const float*)d_in[2];   // [N,32]
    const float* mask      = (const float*)d_in[3];   // [N,1]
    const float* msg_w     = (const float*)d_in[4];   // [2,128,128]
    float*       out       = (float*)d_out;

    const int N = in_sizes[0] / DD;

    __half* msg; float* xbuf;
    cudaGetSymbolAddress((void**)&msg,  g_msg);
    cudaGetSymbolAddress((void**)&xbuf, g_x);

    const int smemBytes = (DD * LDS + TROWS * LDS) * sizeof(float);  // ~104.5 KB
    static int attrSet = 0;
    if (!attrSet) {
        cudaFuncSetAttribute(gemm_tf32_kernel,
                             cudaFuncAttributeMaxDynamicSharedMemorySize, smemBytes);
        attrSet = 1;
    }

    const int nTiles = (N + TROWS - 1) / TROWS;
    int gemmBlocks = 296;                        // persistent: 2 CTAs/SM
    if (gemmBlocks > nTiles) gemmBlocks = nTiles;
    const int aggBlocks = (N * 32 + 255) / 256;

    const float* W0 = msg_w;
    const float* W1 = msg_w + DD * DD;

    gemm_tf32_kernel<<<gemmBlocks, 256, smemBytes>>>(node_repr, W0, mask, msg, N, 1);
    agg_kernel     <<<aggBlocks, 256>>>(msg, adj_mat, weight, mask, xbuf, N, 1);
    gemm_tf32_kernel<<<gemmBlocks, 256, smemBytes>>>(xbuf, W1, mask, msg, N, 0);
    agg_kernel     <<<aggBlocks, 256>>>(msg, adj_mat, weight, mask, out, N, 0);
}

// round 6
// speedup vs baseline: 1.1462x; 1.1462x over previous
#include <cuda_runtime.h>
#include <cuda_fp16.h>
#include <mma.h>
#include <math.h>

using namespace nvcuda;

// ---------------------------------------------------------------------------
// RiemannianGNN, 2-layer Poincare GNN — fused per-layer kernel.
// Algebraic reorder: sum_k w*(t[adj]@W) == (sum_k w*t[adj])@W, so each layer is
//   g[n]  = sum_k w[n,k]*maskfac[adj]* t_in[adj[n,k]]   (gather, fp32)
//   y     = g @ W                                       (tf32 WMMA, per-tile)
//   out   = relu(expmap(y*mask)*mask)*mask  (+ fused logmap*mask for layer 0)
// One kernel per layer; no intermediate msg buffer.
// ---------------------------------------------------------------------------

#define NMAX 50000
#define DD 128
#define KK 32
#define TR 64          // nodes (rows) per block
#define LDS 132        // padded smem stride in floats (132*4B: +4 pad, float4-aligned)

__device__ __align__(16) float g_x[NMAX * DD];   // t1 between layers

__global__ __launch_bounds__(256, 2) void layer_kernel(
    const float* __restrict__ xin, const int* __restrict__ adj,
    const float* __restrict__ wgt, const float* __restrict__ mask,
    const float* __restrict__ W, float* __restrict__ outx,
    int N, int layer0)
{
    extern __shared__ float sm[];
    float* Ws = sm;                 // 128 x LDS (tf32 values)
    float* As = sm + DD * LDS;      // TR x LDS  (tf32 gathered tile / fp32 results)

    const int tid  = threadIdx.x;
    const int w    = tid >> 5;
    const int lane = tid & 31;
    const int n0   = blockIdx.x * TR;

    // ---- stage W once per block (convert to tf32) ----
    for (int i = tid; i < DD * DD / 4; i += 256) {
        int r = i >> 5, c4 = i & 31;
        float4 v = ((const float4*)W)[r * 32 + c4];
        float* dst = Ws + r * LDS + c4 * 4;
        dst[0] = wmma::__float_to_tf32(v.x);
        dst[1] = wmma::__float_to_tf32(v.y);
        dst[2] = wmma::__float_to_tf32(v.z);
        dst[3] = wmma::__float_to_tf32(v.w);
    }

    // ---- phase A: gather-aggregate, warp per node, 8 nodes per warp ----
    #pragma unroll
    for (int i = 0; i < TR / 8; i++) {
        const int r = w * (TR / 8) + i;
        const int n = n0 + r;

        float4 acc = make_float4(0.f, 0.f, 0.f, 0.f);
        if (n < N) {
            const int   myIdx = adj[n * KK + lane];
            const float myW   = wgt[n * KK + lane];
            const float ma    = mask[myIdx];
            // layer0 reads raw node_repr: fold t-mask AND msg-mask -> w*ma*ma
            // layer1 reads t1 (one mask already inside): fold msg-mask -> w*ma
            const float wEff  = layer0 ? myW * ma * ma : myW * ma;

            #pragma unroll
            for (int j = 0; j < KK; j++) {
                int   nb = __shfl_sync(0xffffffffu, myIdx, j);
                float wj = __shfl_sync(0xffffffffu, wEff,  j);
                float4 v = __ldg(((const float4*)(xin + (size_t)nb * DD)) + lane);
                acc.x = fmaf(wj, v.x, acc.x);
                acc.y = fmaf(wj, v.y, acc.y);
                acc.z = fmaf(wj, v.z, acc.z);
                acc.w = fmaf(wj, v.w, acc.w);
            }
        }
        float4 t;
        t.x = wmma::__float_to_tf32(acc.x);
        t.y = wmma::__float_to_tf32(acc.y);
        t.z = wmma::__float_to_tf32(acc.z);
        t.w = wmma::__float_to_tf32(acc.w);
        *(float4*)(As + r * LDS + lane * 4) = t;
    }
    __syncthreads();

    // ---- phase B: tile GEMM  (8 warps: 4 row-groups x 2 col-groups) ----
    {
        const int rw = w >> 1;          // rows rw*16 .. rw*16+15
        const int cw = w & 1;           // cols cw*64 .. cw*64+63

        wmma::fragment<wmma::matrix_a, 16, 16, 8, wmma::precision::tf32, wmma::row_major> aF;
        wmma::fragment<wmma::matrix_b, 16, 16, 8, wmma::precision::tf32, wmma::row_major> bF[4];
        wmma::fragment<wmma::accumulator, 16, 16, 8, float> acc[4];
        #pragma unroll
        for (int j = 0; j < 4; j++) wmma::fill_fragment(acc[j], 0.0f);

        #pragma unroll
        for (int ks = 0; ks < DD / 8; ks++) {
            const int kOff = ks * 8;
            wmma::load_matrix_sync(aF, As + (rw * 16) * LDS + kOff, LDS);
            #pragma unroll
            for (int j = 0; j < 4; j++)
                wmma::load_matrix_sync(bF[j], Ws + kOff * LDS + cw * 64 + j * 16, LDS);
            #pragma unroll
            for (int j = 0; j < 4; j++)
                wmma::mma_sync(acc[j], aF, bF[j], acc[j]);
        }

        __syncthreads();   // done reading As as A-operand
        #pragma unroll
        for (int j = 0; j < 4; j++)
            wmma::store_matrix_sync(As + (rw * 16) * LDS + cw * 64 + j * 16,
                                    acc[j], LDS, wmma::mem_row_major);
    }
    __syncthreads();

    // ---- phase C: pointwise epilogue, warp per row ----
    #pragma unroll
    for (int i = 0; i < TR / 8; i++) {
        const int r = w * (TR / 8) + i;
        const int n = n0 + r;
        if (n >= N) continue;

        const float m = mask[n];
        float4 y = *(float4*)(As + r * LDS + lane * 4);
        y.x *= m; y.y *= m; y.z *= m; y.w *= m;          // combined = (...)*mask

        // expmap_zero: tanh(clip(||v||,eps,15)) * v / max(||v||,eps), then *mask
        float ss = y.x * y.x + y.y * y.y + y.z * y.z + y.w * y.w;
        #pragma unroll
        for (int o = 16; o > 0; o >>= 1) ss += __shfl_xor_sync(0xffffffffu, ss, o);
        float n1  = sqrtf(ss);
        float nc1 = fminf(fmaxf(n1, 1e-5f), 15.0f);
        float s1  = tanhf(nc1) / fmaxf(n1, 1e-5f) * m;

        float4 e;
        e.x = fmaxf(y.x * s1, 0.f) * m;   // relu(...)*mask
        e.y = fmaxf(y.y * s1, 0.f) * m;
        e.z = fmaxf(y.z * s1, 0.f) * m;
        e.w = fmaxf(y.w * s1, 0.f) * m;

        if (layer0) {
            // next layer's logmap: atanh(clip(||y||,eps,1-1e-5))*y/max(||y||,eps) * mask
            float ss2 = e.x * e.x + e.y * e.y + e.z * e.z + e.w * e.w;
            #pragma unroll
            for (int o = 16; o > 0; o >>= 1) ss2 += __shfl_xor_sync(0xffffffffu, ss2, o);
            float n2  = sqrtf(ss2);
            float nc2 = fminf(fmaxf(n2, 1e-5f), 1.0f - 1e-5f);
            float s2  = atanhf(nc2) / fmaxf(n2, 1e-5f) * m;
            e.x *= s2; e.y *= s2; e.z *= s2; e.w *= s2;
        }

        ((float4*)outx)[n * 32 + lane] = e;
    }
}

// ---------------------------------------------------------------------------

extern "C" void kernel_launch(void* const* d_in, const int* in_sizes, int n_in,
                              void* d_out, int out_size)
{
    const float* node_repr = (const float*)d_in[0];   // [N,128]
    const int*   adj_mat   = (const int*)  d_in[1];   // [N,32]
    const float* weight    = (const float*)d_in[2];   // [N,32]
    const float* mask      = (const float*)d_in[3];   // [N,1]
    const float* msg_w     = (const float*)d_in[4];   // [2,128,128]
    float*       out       = (float*)d_out;

    const int N = in_sizes[0] / DD;

    float* xbuf;
    cudaGetSymbolAddress((void**)&xbuf, g_x);

    const int smemBytes = (DD + TR) * LDS * sizeof(float);   // ~101 KB
    static int attrSet = 0;
    if (!attrSet) {
        cudaFuncSetAttribute(layer_kernel,
                             cudaFuncAttributeMaxDynamicSharedMemorySize, smemBytes);
        attrSet = 1;
    }

    const int blocks = (N + TR - 1) / TR;
    const float* W0 = msg_w;
    const float* W1 = msg_w + DD * DD;

    // layer 0: gather node_repr, @W0, expmap/relu + fused logmap -> t1
    layer_kernel<<<blocks, 256, smemBytes>>>(node_repr, adj_mat, weight, mask,
                                             W0, xbuf, N, 1);
    // layer 1: gather t1, @W1, expmap/relu -> out
    layer_kernel<<<blocks, 256, smemBytes>>>(xbuf, adj_mat, weight, mask,
                                             W1, out, N, 0);
}

// round 7
// speedup vs baseline: 1.2812x; 1.1178x over previous
#include <cuda_runtime.h>
#include <mma.h>
#include <math.h>

using namespace nvcuda;

// ---------------------------------------------------------------------------
// RiemannianGNN, 2-layer Poincare GNN — split kernels, algebra-optimized.
//   gemm:  msg_raw = x @ W            (pure tf32 WMMA, no masks, no epilogue)
//   agg:   combined = sum_k (w*maskfac[adj]) * msg_raw[adj],  * mask[n]
//          out = relu(expmap(.)*mask)*mask   (+ fused logmap*mask for layer 0)
// Mask algebra: msg-mask and t-mask fold into the gather weight
//   (mask[adj]^2 for layer 0 since x is raw node_repr; mask[adj] for layer 1).
// GEMM is persistent (W staged once/block), NO syncs in the tile loop:
// A fragments from global, B from smem, C straight to global.
// ---------------------------------------------------------------------------

#define NMAX 50000
#define DD 128
#define KK 32
#define LDSW 132        // padded W stride (floats)
#define TROWS 64        // rows per gemm tile

__device__ __align__(16) float g_msg[NMAX * DD];
__device__ __align__(16) float g_x[NMAX * DD];

// ---------------- persistent pure GEMM: out = x @ W ------------------------
__global__ __launch_bounds__(256) void gemm_kernel(
    const float* __restrict__ x, const float* __restrict__ W,
    float* __restrict__ out, int N)
{
    extern __shared__ float Ws[];   // 128 x LDSW
    const int tid = threadIdx.x;

    // stage W once (convert to tf32)
    for (int i = tid; i < DD * DD / 4; i += 256) {
        int r = i >> 5, c4 = i & 31;
        float4 v = ((const float4*)W)[r * 32 + c4];
        float* dst = Ws + r * LDSW + c4 * 4;
        dst[0] = wmma::__float_to_tf32(v.x);
        dst[1] = wmma::__float_to_tf32(v.y);
        dst[2] = wmma::__float_to_tf32(v.z);
        dst[3] = wmma::__float_to_tf32(v.w);
    }
    __syncthreads();   // the ONLY barrier in this kernel

    const int w  = tid >> 5;
    const int rw = w >> 1;       // row group: rows rw*16
    const int cw = w & 1;        // col group: cols cw*64

    const int nTiles = (N + TROWS - 1) / TROWS;

    for (int tile = blockIdx.x; tile < nTiles; tile += gridDim.x) {
        const int r0 = tile * TROWS + rw * 16;
        if (r0 + 16 > N) continue;          // N % 16 == 0: full groups only

        wmma::fragment<wmma::matrix_a, 16, 16, 8, wmma::precision::tf32, wmma::row_major> aF;
        wmma::fragment<wmma::matrix_b, 16, 16, 8, wmma::precision::tf32, wmma::row_major> bF[4];
        wmma::fragment<wmma::accumulator, 16, 16, 8, float> acc[4];
        #pragma unroll
        for (int j = 0; j < 4; j++) wmma::fill_fragment(acc[j], 0.0f);

        #pragma unroll
        for (int ks = 0; ks < DD / 8; ks++) {
            const int kOff = ks * 8;
            // A fragment straight from global (rows stream once; L2-backed)
            wmma::load_matrix_sync(aF, x + (size_t)r0 * DD + kOff, DD);
            #pragma unroll
            for (int j = 0; j < 4; j++)
                wmma::load_matrix_sync(bF[j], Ws + kOff * LDSW + cw * 64 + j * 16, LDSW);
            #pragma unroll
            for (int j = 0; j < 4; j++)
                wmma::mma_sync(acc[j], aF, bF[j], acc[j]);
        }

        #pragma unroll
        for (int j = 0; j < 4; j++)
            wmma::store_matrix_sync(out + (size_t)r0 * DD + cw * 64 + j * 16,
                                    acc[j], DD, wmma::mem_row_major);
    }
}

// ---------------- Aggregation + expmap + relu (+ fused logmap) -------------
// one warp per node; lane l holds cols 4l..4l+3
__global__ __launch_bounds__(256) void agg_kernel(
    const float* __restrict__ msg, const int* __restrict__ adj,
    const float* __restrict__ wgt, const float* __restrict__ mask,
    float* __restrict__ out, int N, int layer0)
{
    const int warp = (blockIdx.x * blockDim.x + threadIdx.x) >> 5;
    const int lane = threadIdx.x & 31;
    if (warp >= N) return;

    const int   myIdx = adj[warp * KK + lane];
    const float ma    = mask[myIdx];
    // fold t-mask and msg-mask of the gathered rows into the weight
    const float myW   = wgt[warp * KK + lane] * (layer0 ? ma * ma : ma);

    float4 acc = make_float4(0.f, 0.f, 0.f, 0.f);
    #pragma unroll
    for (int j = 0; j < KK; j++) {
        int   nb = __shfl_sync(0xffffffffu, myIdx, j);
        float wj = __shfl_sync(0xffffffffu, myW,   j);
        float4 v = __ldg(((const float4*)(msg + (size_t)nb * DD)) + lane);
        acc.x = fmaf(wj, v.x, acc.x);
        acc.y = fmaf(wj, v.y, acc.y);
        acc.z = fmaf(wj, v.z, acc.z);
        acc.w = fmaf(wj, v.w, acc.w);
    }

    const float m = mask[warp];
    acc.x *= m; acc.y *= m; acc.z *= m; acc.w *= m;   // combined = (...)*mask

    // expmap_zero: tanh(clip(||v||,eps,15)) * v / max(||v||,eps), then *mask
    float ss = acc.x * acc.x + acc.y * acc.y + acc.z * acc.z + acc.w * acc.w;
    #pragma unroll
    for (int o = 16; o > 0; o >>= 1) ss += __shfl_xor_sync(0xffffffffu, ss, o);
    float n1  = sqrtf(ss);
    float nc1 = fminf(fmaxf(n1, 1e-5f), 15.0f);
    float s1  = tanhf(nc1) / fmaxf(n1, 1e-5f) * m;

    float4 e;
    e.x = fmaxf(acc.x * s1, 0.f) * m;
    e.y = fmaxf(acc.y * s1, 0.f) * m;
    e.z = fmaxf(acc.z * s1, 0.f) * m;
    e.w = fmaxf(acc.w * s1, 0.f) * m;

    if (layer0) {
        // next layer's logmap: atanh(clip(||y||,eps,1-1e-5))*y/max(||y||,eps) * mask
        float ss2 = e.x * e.x + e.y * e.y + e.z * e.z + e.w * e.w;
        #pragma unroll
        for (int o = 16; o > 0; o >>= 1) ss2 += __shfl_xor_sync(0xffffffffu, ss2, o);
        float n2  = sqrtf(ss2);
        float nc2 = fminf(fmaxf(n2, 1e-5f), 1.0f - 1e-5f);
        float s2  = atanhf(nc2) / fmaxf(n2, 1e-5f) * m;
        e.x *= s2; e.y *= s2; e.z *= s2; e.w *= s2;
    }

    ((float4*)out)[warp * 32 + lane] = e;
}

// ---------------------------------------------------------------------------

extern "C" void kernel_launch(void* const* d_in, const int* in_sizes, int n_in,
                              void* d_out, int out_size)
{
    const float* node_repr = (const float*)d_in[0];   // [N,128]
    const int*   adj_mat   = (const int*)  d_in[1];   // [N,32]
    const float* weight    = (const float*)d_in[2];   // [N,32]
    const float* mask      = (const float*)d_in[3];   // [N,1]
    const float* msg_w     = (const float*)d_in[4];   // [2,128,128]
    float*       out       = (float*)d_out;

    const int N = in_sizes[0] / DD;

    float* msg; float* xbuf;
    cudaGetSymbolAddress((void**)&msg,  g_msg);
    cudaGetSymbolAddress((void**)&xbuf, g_x);

    const int smemBytes = DD * LDSW * sizeof(float);   // 67.6 KB -> 2 CTA/SM
    static int attrSet = 0;
    if (!attrSet) {
        cudaFuncSetAttribute(gemm_kernel,
                             cudaFuncAttributeMaxDynamicSharedMemorySize, smemBytes);
        attrSet = 1;
    }

    const int nTiles = (N + TROWS - 1) / TROWS;
    int gemmBlocks = 296;                // persistent, 2 CTA/SM
    if (gemmBlocks > nTiles) gemmBlocks = nTiles;
    const int aggBlocks = (N * 32 + 255) / 256;

    const float* W0 = msg_w;
    const float* W1 = msg_w + DD * DD;

    // layer 0: msg = node_repr @ W0 (pure); agg folds masks, fuses logmap
    gemm_kernel<<<gemmBlocks, 256, smemBytes>>>(node_repr, W0, msg, N);
    agg_kernel <<<aggBlocks, 256>>>(msg, adj_mat, weight, mask, xbuf, N, 1);
    // layer 1
    gemm_kernel<<<gemmBlocks, 256, smemBytes>>>(xbuf, W1, msg, N);
    agg_kernel <<<aggBlocks, 256>>>(msg, adj_mat, weight, mask, out, N, 0);
}